// round 13
// baseline (speedup 1.0000x reference)
#include <cuda_runtime.h>
#include <math.h>

#define N_TOK 8192
#define DIM   4096
#define NEXP  16
#define TPB   256
#define NWARP 8
#define TOK   32
#define KSL   (DIM / NWARP)       /* 512 k per warp */
#define KT    32                  /* k per tile */
#define NT    (KSL / KT)          /* 16 tiles */
#define XSTR  33                  /* x smem row stride (words) — conflict-free */

#define W_XB  (KT * XSTR)         /* 1056 f : one x buffer */
#define W_GB  (KT * NEXP)         /*  512 f : one gate buffer */
#define W_FL  (2 * W_XB + 2 * W_GB) /* 3136 f per warp */
#define SM_FLOATS (NWARP * W_FL)  /* 25088 f = 100352 B -> 2 CTAs/SM */
#define SM_BYTES  (SM_FLOATS * 4)

#define FMA2(acc, a, b) \
    asm("fma.rn.f32x2 %0, %1, %2, %0;" : "+l"(acc) : "l"(a), "l"(b))

__global__ void __launch_bounds__(TPB, 2)
router_kernel(const float* __restrict__ x, const float* __restrict__ gate,
              float* __restrict__ out, int out_size)
{
    extern __shared__ float sm[];

    const int tid = threadIdx.x;
    const int w = tid >> 5, l = tid & 31;
    const int tokBase = blockIdx.x * TOK;
    const int kw = w * KSL;

    float* xb0 = sm + w * W_FL;
    float* xb1 = xb0 + W_XB;
    float* gb0 = xb1 + W_XB;
    float* gb1 = gb0 + W_GB;

    // staging roles
    const int tokr = l >> 3;      // 0..3
    const int kq8  = l & 7;       // 0..7 (k quad within tile)
    // compute roles: lane = kq*8 + tg*2 + eg
    const int kq = l >> 3;        // 0..3 k-interleave
    const int tg = (l >> 1) & 3;  // token octet: tokens 8tg..8tg+7
    const int eg = l & 1;         // expert half: experts 8eg..8eg+7

    // acc[i*4+ep]: token 8tg+i, expert pair {8eg+2ep, 8eg+2ep+1}
    unsigned long long acc[32];
#pragma unroll
    for (int i = 0; i < 32; i++) acc[i] = 0ull;

    const float* xlane = x + (size_t)(tokBase + tokr) * DIM + kw + 4 * kq8;
    const float4* glane = (const float4*)(gate + (size_t)kw * NEXP) + l;

    /* ---- staging macros: 8-register chunks ---- */
    // x quarter qd = token rows 4*(2qd+rr)+tokr, rr=0..1
#define LDG_XQ(r2, tt, qd)                                                     \
    {                                                                          \
        _Pragma("unroll")                                                      \
        for (int rr = 0; rr < 2; rr++)                                         \
            r2[rr] = *(const float4*)(xlane                                    \
                        + (size_t)(4 * (2*(qd) + rr)) * DIM + (tt) * KT);      \
    }
#define STS_XQ(r2, xbuf, qd)                                                   \
    {                                                                          \
        _Pragma("unroll")                                                      \
        for (int rr = 0; rr < 2; rr++) {                                       \
            float* col = (xbuf) + (4 * (2*(qd) + rr) + tokr);                  \
            col[(4 * kq8 + 0) * XSTR] = r2[rr].x;                              \
            col[(4 * kq8 + 1) * XSTR] = r2[rr].y;                              \
            col[(4 * kq8 + 2) * XSTR] = r2[rr].z;                              \
            col[(4 * kq8 + 3) * XSTR] = r2[rr].w;                              \
        }                                                                      \
    }
    // gate half hh = float4 chunks 2hh, 2hh+1 of the 128-float4 tile
#define LDG_GH(r2, tt, hh)                                                     \
    {                                                                          \
        _Pragma("unroll")                                                      \
        for (int c = 0; c < 2; c++)                                            \
            r2[c] = glane[(size_t)(tt) * 128 + (2*(hh) + c) * 32];             \
    }
#define STS_GH(r2, gbuf, hh)                                                   \
    {                                                                          \
        _Pragma("unroll")                                                      \
        for (int c = 0; c < 2; c++)                                            \
            ((float4*)(gbuf))[(2*(hh) + c) * 32 + l] = r2[c];                  \
    }
    /* compute batch with gate software-pipelined one batch ahead (Gc -> Gn) */
#define BATCHP(xs, gs, b)                                                      \
    {                                                                          \
        ulonglong2 Gn0, Gn1;                                                   \
        if ((b) < 7) {                                                         \
            const ulonglong2* gpn =                                            \
                (const ulonglong2*)((gs) + (4*((b)+1) + kq) * NEXP + 8 * eg);  \
            Gn0 = gpn[0]; Gn1 = gpn[1];                                        \
        }                                                                      \
        const float* xrow = (xs) + (4*(b) + kq) * XSTR + 8 * tg;               \
        _Pragma("unroll")                                                      \
        for (int i = 0; i < 8; i++) {                                          \
            float xv = xrow[i];                                                \
            unsigned long long xd;                                             \
            asm("mov.b64 %0, {%1,%1};" : "=l"(xd) : "f"(xv));                  \
            FMA2(acc[i * 4 + 0], xd, Gc0.x);                                   \
            FMA2(acc[i * 4 + 1], xd, Gc0.y);                                   \
            FMA2(acc[i * 4 + 2], xd, Gc1.x);                                   \
            FMA2(acc[i * 4 + 3], xd, Gc1.y);                                   \
        }                                                                      \
        if ((b) < 7) { Gc0 = Gn0; Gc1 = Gn1; }                                 \
    }

    // ---- prologue: stage tile 0 into buffer 0 ----
    {
        float4 A[2], B[2];
        LDG_XQ(A, 0, 0); LDG_XQ(B, 0, 1);
        STS_XQ(A, xb0, 0); STS_XQ(B, xb0, 1);
        LDG_XQ(A, 0, 2); LDG_XQ(B, 0, 3);
        STS_XQ(A, xb0, 2); STS_XQ(B, xb0, 3);
        LDG_GH(A, 0, 0); LDG_GH(B, 0, 1);
        STS_GH(A, gb0, 0); STS_GH(B, gb0, 1);
    }
    __syncwarp();

#pragma unroll 1
    for (int t = 0; t < NT - 1; t++) {
        float* xs = (t & 1) ? xb1 : xb0;
        float* gs = (t & 1) ? gb1 : gb0;
        float* xn = (t & 1) ? xb0 : xb1;   // next-tile buffers
        float* gn = (t & 1) ? gb0 : gb1;

        float4 A[2], B[2];                  // 16 transient staging regs

        // gate pipeline seed: batch 0 of this tile
        ulonglong2 Gc0, Gc1;
        {
            const ulonglong2* gp0 = (const ulonglong2*)(gs + kq * NEXP + 8 * eg);
            Gc0 = gp0[0]; Gc1 = gp0[1];
        }

        LDG_XQ(A, t + 1, 0);
        BATCHP(xs, gs, 0);
        LDG_XQ(B, t + 1, 1);
        BATCHP(xs, gs, 1);
        STS_XQ(A, xn, 0); LDG_XQ(A, t + 1, 2);
        BATCHP(xs, gs, 2);
        STS_XQ(B, xn, 1); LDG_XQ(B, t + 1, 3);
        BATCHP(xs, gs, 3);
        STS_XQ(A, xn, 2); LDG_GH(A, t + 1, 0);
        BATCHP(xs, gs, 4);
        STS_XQ(B, xn, 3); LDG_GH(B, t + 1, 1);
        BATCHP(xs, gs, 5);
        BATCHP(xs, gs, 6);
        STS_GH(A, gn, 0);
        BATCHP(xs, gs, 7);
        STS_GH(B, gn, 1);

        __syncwarp();   // all lanes' next-tile STS visible before next compute
    }

    // ---- peeled last tile: compute only ----
    {
        const int t = NT - 1;
        float* xs = (t & 1) ? xb1 : xb0;
        float* gs = (t & 1) ? gb1 : gb0;
        ulonglong2 Gc0, Gc1;
        {
            const ulonglong2* gp0 = (const ulonglong2*)(gs + kq * NEXP + 8 * eg);
            Gc0 = gp0[0]; Gc1 = gp0[1];
        }
        BATCHP(xs, gs, 0); BATCHP(xs, gs, 1); BATCHP(xs, gs, 2); BATCHP(xs, gs, 3);
        BATCHP(xs, gs, 4); BATCHP(xs, gs, 5); BATCHP(xs, gs, 6); BATCHP(xs, gs, 7);
    }

    // ---- butterfly-reduce the 4-way k-interleave (lanes xor 8, 16) ----
#pragma unroll
    for (int i = 0; i < 32; i++) {
        float2 v = *(float2*)&acc[i];
        v.x += __shfl_xor_sync(0xffffffffu, v.x, 8);
        v.y += __shfl_xor_sync(0xffffffffu, v.y, 8);
        v.x += __shfl_xor_sync(0xffffffffu, v.x, 16);
        v.y += __shfl_xor_sync(0xffffffffu, v.y, 16);
        *(float2*)&acc[i] = v;
    }

    // ---- epilogue smem aliases the tile buffers (all warps done with them) ----
    __syncthreads();
    float* part = sm;                          // [NWARP][TOK][16]
    float* lg   = sm + NWARP * TOK * NEXP;     // [TOK][16]

    if (kq == 0) {
#pragma unroll
        for (int i = 0; i < 8; i++) {
            float* dst = part + (size_t)(w * TOK + 8 * tg + i) * NEXP + 8 * eg;
#pragma unroll
            for (int ep = 0; ep < 4; ep++)
                *(float2*)(dst + 2 * ep) = *(float2*)&acc[i * 4 + ep];
        }
    }
    __syncthreads();

    // ---- deterministic 8-warp tree reduce: thread -> (token, expert pair) ----
    {
        int tok = tid >> 3, e2 = (tid & 7) * 2;
        float2 s = make_float2(0.f, 0.f);
#pragma unroll
        for (int ww = 0; ww < NWARP; ww++) {
            float2 v = *(const float2*)(part + (size_t)(ww * TOK + tok) * NEXP + e2);
            s.x += v.x; s.y += v.y;
        }
        __syncthreads();
        *(float2*)(lg + tok * NEXP + e2) = s;
    }
    __syncthreads();

    // ---- top-2 + sigmoid + transposed score writes ----
    if (tid < TOK) {
        int t = tid;
        float v[NEXP];
#pragma unroll
        for (int e = 0; e < NEXP; e++) v[e] = lg[t * NEXP + e];
        float v1 = -INFINITY, v2 = -INFINITY;
        int   i1 = -1,        i2 = -1;
#pragma unroll
        for (int e = 0; e < NEXP; e++) {
            float tv = v[e];
            if (tv > v1)      { v2 = v1; i2 = i1; v1 = tv; i1 = e; }
            else if (tv > v2) { v2 = tv; i2 = e; }
        }
        int gtok = tokBase + t;
#pragma unroll
        for (int e = 0; e < NEXP; e++) {
            float sc = (e == i1 || e == i2) ? (1.0f / (1.0f + expf(-v[e]))) : 0.0f;
            out[(size_t)e * N_TOK + gtok] = sc;   // 32 consecutive tokens: coalesced
        }
    }

    // ---- token_indices (second output region), values as floats ----
    if (out_size >= 2 * NEXP * N_TOK) {
        int e  = tid >> 4;            // 0..15
        int c2 = (tid & 15) * 2;      // token pair within block
        int gtok = tokBase + c2;
        float2 fv = make_float2((float)gtok, (float)(gtok + 1));
        *(float2*)(out + (size_t)NEXP * N_TOK + (size_t)e * N_TOK + gtok) = fv;
    }
}

extern "C" void kernel_launch(void* const* d_in, const int* in_sizes, int n_in,
                              void* d_out, int out_size)
{
    const float* x    = (const float*)d_in[0];
    const float* gate = (const float*)d_in[1];
    float* out = (float*)d_out;

    cudaFuncSetAttribute(router_kernel,
                         cudaFuncAttributeMaxDynamicSharedMemorySize, SM_BYTES);

    dim3 grid(N_TOK / TOK);   // 256 blocks, 2 CTAs/SM
    dim3 block(TPB);
    router_kernel<<<grid, block, SM_BYTES>>>(x, gate, out, out_size);
}

// round 14
// speedup vs baseline: 1.2850x; 1.2850x over previous
#include <cuda_runtime.h>
#include <math.h>

#define N_TOK 8192
#define DIM   4096
#define NEXP  16
#define TPB   256
#define NWARP 8
#define TOK   32
#define KSL   (DIM / NWARP)       /* 512 k per warp */
#define KT    32                  /* k per tile */
#define NT    (KSL / KT)          /* 16 tiles */
#define XSTR  33                  /* x smem row stride (words) — conflict-free */

#define W_XB  (KT * XSTR)         /* 1056 f : one x buffer */
#define W_GB  (KT * NEXP)         /*  512 f : one gate buffer */
#define W_FL  (2 * W_XB + 2 * W_GB) /* 3136 f per warp */
#define SM_FLOATS (NWARP * W_FL)  /* 25088 f = 100352 B -> 2 CTAs/SM */
#define SM_BYTES  (SM_FLOATS * 4)

#define FMA2(acc, a, b) \
    asm("fma.rn.f32x2 %0, %1, %2, %0;" : "+l"(acc) : "l"(a), "l"(b))

__global__ void __launch_bounds__(TPB, 2)
router_kernel(const float* __restrict__ x, const float* __restrict__ gate,
              float* __restrict__ out, int out_size)
{
    extern __shared__ float sm[];

    const int tid = threadIdx.x;
    const int w = tid >> 5, l = tid & 31;
    const int tokBase = blockIdx.x * TOK;
    const int kw = w * KSL;

    float* xb0 = sm + w * W_FL;
    float* xb1 = xb0 + W_XB;
    float* gb0 = xb1 + W_XB;
    float* gb1 = gb0 + W_GB;

    // staging roles
    const int tokr = l >> 3;      // 0..3
    const int kq8  = l & 7;       // 0..7 (k quad within tile)
    // compute roles: lane = kq*8 + tg*2 + eg
    const int kq = l >> 3;        // 0..3 k-interleave
    const int tg = (l >> 1) & 3;  // token octet: tokens 8tg..8tg+7
    const int eg = l & 1;         // expert half: experts 8eg..8eg+7

    // acc[i*4+ep]: token 8tg+i, expert pair {8eg+2ep, 8eg+2ep+1}
    unsigned long long acc[32];
#pragma unroll
    for (int i = 0; i < 32; i++) acc[i] = 0ull;

    const float* xlane = x + (size_t)(tokBase + tokr) * DIM + kw + 4 * kq8;
    const float4* glane = (const float4*)(gate + (size_t)kw * NEXP) + l;

    // ---- macros: 16-register staging chunks ----
    // x half h (rows 4*(4h+rr)+tokr, rr=0..3) of tile tt into xr4
#define LDG_XHALF(xr4, tt, h)                                                  \
    {                                                                          \
        _Pragma("unroll")                                                      \
        for (int rr = 0; rr < 4; rr++)                                         \
            xr4[rr] = *(const float4*)(xlane + (size_t)(4 * (4*(h) + rr)) * DIM \
                                       + (tt) * KT);                           \
    }
#define STS_XHALF(xr4, xbuf, h)                                                \
    {                                                                          \
        _Pragma("unroll")                                                      \
        for (int rr = 0; rr < 4; rr++) {                                       \
            float* col = (xbuf) + (4 * (4*(h) + rr) + tokr);                   \
            col[(4 * kq8 + 0) * XSTR] = xr4[rr].x;                             \
            col[(4 * kq8 + 1) * XSTR] = xr4[rr].y;                             \
            col[(4 * kq8 + 2) * XSTR] = xr4[rr].z;                             \
            col[(4 * kq8 + 3) * XSTR] = xr4[rr].w;                             \
        }                                                                      \
    }
#define LDG_GATE(gr4, tt)                                                      \
    {                                                                          \
        _Pragma("unroll")                                                      \
        for (int c = 0; c < 4; c++)                                            \
            gr4[c] = glane[(size_t)(tt) * 128 + c * 32];                       \
    }
#define STS_GATE(gr4, gbuf)                                                    \
    {                                                                          \
        _Pragma("unroll")                                                      \
        for (int c = 0; c < 4; c++)                                            \
            ((float4*)(gbuf))[c * 32 + l] = gr4[c];                            \
    }
    // one compute batch: lane's k = 4b+kq of tile buffers (xs, gs)
#define BATCH(xs, gs, b)                                                       \
    {                                                                          \
        const ulonglong2* gp =                                                 \
            (const ulonglong2*)((gs) + (4*(b) + kq) * NEXP + 8 * eg);          \
        ulonglong2 Ga = gp[0], Gb = gp[1];                                     \
        const float* xrow = (xs) + (4*(b) + kq) * XSTR + 8 * tg;               \
        _Pragma("unroll")                                                      \
        for (int i = 0; i < 8; i++) {                                          \
            float xv = xrow[i];                                                \
            unsigned long long xd;                                             \
            asm("mov.b64 %0, {%1,%1};" : "=l"(xd) : "f"(xv));                  \
            FMA2(acc[i * 4 + 0], xd, Ga.x);                                    \
            FMA2(acc[i * 4 + 1], xd, Ga.y);                                    \
            FMA2(acc[i * 4 + 2], xd, Gb.x);                                    \
            FMA2(acc[i * 4 + 3], xd, Gb.y);                                    \
        }                                                                      \
    }

    // ---- prologue: stage tile 0 into buffer 0 ----
    {
        float4 xr4[4], gr4[4];
        LDG_XHALF(xr4, 0, 0);
        LDG_GATE(gr4, 0);
        STS_XHALF(xr4, xb0, 0);
        LDG_XHALF(xr4, 0, 1);
        STS_GATE(gr4, gb0);
        STS_XHALF(xr4, xb0, 1);
    }
    __syncwarp();

#pragma unroll 1
    for (int t = 0; t < NT; t++) {
        float* xs = (t & 1) ? xb1 : xb0;
        float* gs = (t & 1) ? gb1 : gb0;
        float* xn = (t & 1) ? xb0 : xb1;   // next-tile buffers
        float* gn = (t & 1) ? gb0 : gb1;
        const int more = (t + 1 < NT);

        float4 s4[4];                       // 16 transient staging regs

        BATCH(xs, gs, 0);
        if (more) LDG_XHALF(s4, t + 1, 0);
        BATCH(xs, gs, 1);
        BATCH(xs, gs, 2);
        if (more) STS_XHALF(s4, xn, 0);
        BATCH(xs, gs, 3);
        if (more) LDG_GATE(s4, t + 1);
        BATCH(xs, gs, 4);
        BATCH(xs, gs, 5);
        if (more) STS_GATE(s4, gn);
        if (more) LDG_XHALF(s4, t + 1, 1);
        BATCH(xs, gs, 6);
        BATCH(xs, gs, 7);
        if (more) STS_XHALF(s4, xn, 1);

        __syncwarp();   // all lanes' next-tile STS visible before next compute
    }

    // ---- butterfly-reduce the 4-way k-interleave (lanes xor 8, 16) ----
#pragma unroll
    for (int i = 0; i < 32; i++) {
        float2 v = *(float2*)&acc[i];
        v.x += __shfl_xor_sync(0xffffffffu, v.x, 8);
        v.y += __shfl_xor_sync(0xffffffffu, v.y, 8);
        v.x += __shfl_xor_sync(0xffffffffu, v.x, 16);
        v.y += __shfl_xor_sync(0xffffffffu, v.y, 16);
        *(float2*)&acc[i] = v;
    }

    // ---- epilogue smem aliases the tile buffers (all warps done with them) ----
    __syncthreads();
    float* part = sm;                          // [NWARP][TOK][16]
    float* lg   = sm + NWARP * TOK * NEXP;     // [TOK][16]

    if (kq == 0) {
#pragma unroll
        for (int i = 0; i < 8; i++) {
            float* dst = part + (size_t)(w * TOK + 8 * tg + i) * NEXP + 8 * eg;
#pragma unroll
            for (int ep = 0; ep < 4; ep++)
                *(float2*)(dst + 2 * ep) = *(float2*)&acc[i * 4 + ep];
        }
    }
    __syncthreads();

    // ---- deterministic 8-warp tree reduce: thread -> (token, expert pair) ----
    {
        int tok = tid >> 3, e2 = (tid & 7) * 2;
        float2 s = make_float2(0.f, 0.f);
#pragma unroll
        for (int ww = 0; ww < NWARP; ww++) {
            float2 v = *(const float2*)(part + (size_t)(ww * TOK + tok) * NEXP + e2);
            s.x += v.x; s.y += v.y;
        }
        __syncthreads();
        *(float2*)(lg + tok * NEXP + e2) = s;
    }
    __syncthreads();

    // ---- top-2 + sigmoid + transposed score writes ----
    if (tid < TOK) {
        int t = tid;
        float v[NEXP];
#pragma unroll
        for (int e = 0; e < NEXP; e++) v[e] = lg[t * NEXP + e];
        float v1 = -INFINITY, v2 = -INFINITY;
        int   i1 = -1,        i2 = -1;
#pragma unroll
        for (int e = 0; e < NEXP; e++) {
            float tv = v[e];
            if (tv > v1)      { v2 = v1; i2 = i1; v1 = tv; i1 = e; }
            else if (tv > v2) { v2 = tv; i2 = e; }
        }
        int gtok = tokBase + t;
#pragma unroll
        for (int e = 0; e < NEXP; e++) {
            float sc = (e == i1 || e == i2) ? (1.0f / (1.0f + expf(-v[e]))) : 0.0f;
            out[(size_t)e * N_TOK + gtok] = sc;   // 32 consecutive tokens: coalesced
        }
    }

    // ---- token_indices (second output region), values as floats ----
    if (out_size >= 2 * NEXP * N_TOK) {
        int e  = tid >> 4;            // 0..15
        int c2 = (tid & 15) * 2;      // token pair within block
        int gtok = tokBase + c2;
        float2 fv = make_float2((float)gtok, (float)(gtok + 1));
        *(float2*)(out + (size_t)NEXP * N_TOK + (size_t)e * N_TOK + gtok) = fv;
    }
}

extern "C" void kernel_launch(void* const* d_in, const int* in_sizes, int n_in,
                              void* d_out, int out_size)
{
    const float* x    = (const float*)d_in[0];
    const float* gate = (const float*)d_in[1];
    float* out = (float*)d_out;

    cudaFuncSetAttribute(router_kernel,
                         cudaFuncAttributeMaxDynamicSharedMemorySize, SM_BYTES);

    dim3 grid(N_TOK / TOK);   // 256 blocks, 2 CTAs/SM
    dim3 block(TPB);
    router_kernel<<<grid, block, SM_BYTES>>>(x, gate, out, out_size);
}